// round 6
// baseline (speedup 1.0000x reference)
#include <cuda_runtime.h>
#include <cuda_fp16.h>
#include <cstdint>

// ---------------------------------------------------------------------------
// GCN hybrid path:
//   xh = fp16(x * out_norm)                      [convert]
//   agg1 = fp32(Agg(xh)) * in_norm               [fp16 gather, fp32 accum/out]
//   h1h = fp16(relu(agg1 @tf32 w1 + b1) * out_norm)
//   agg2 = fp32(Agg(h1h)) * in_norm
//   h2  = fp32(relu(agg2 @tf32 w2 + b2))
//   h3  = fp32(relu(h2 @tf32 wm1 + bm1))
//   out = h3 @tf32 wm2 + bm2
// Only the GATHERED features are fp16 (halves agg L2 traffic); GEMM inputs
// stay fp32->tf32 exactly as the proven R3 kernel.
// ---------------------------------------------------------------------------

#define N_MAX 100000
#define E_MAX 3200000

__device__ int    g_deg_in[N_MAX];
__device__ int    g_deg_out[N_MAX];
__device__ int    g_row_ptr[N_MAX + 1];
__device__ int    g_cursor[N_MAX];
__device__ int    g_sorted_src[E_MAX];
__device__ float  g_out_norm[N_MAX];
__device__ float  g_in_norm[N_MAX];
__device__ __half g_xh[(size_t)N_MAX * 128];   // pass-1 gather features
__device__ __half g_h1h[(size_t)N_MAX * 128];  // pass-2 gather features
__device__ float  g_aggf[(size_t)N_MAX * 128]; // agg output (GEMM A input)
__device__ float  g_h[(size_t)N_MAX * 128];    // h2
__device__ float  g_h3[(size_t)N_MAX * 256];   // MLP hidden

// ---------------------------------------------------------------------------
__global__ void zero_deg_kernel(int n, int* deg_in, int* deg_out) {
    int i = blockIdx.x * blockDim.x + threadIdx.x;
    if (i < n) { deg_in[i] = 0; deg_out[i] = 0; }
}

__global__ void hist_kernel(int e, const int* __restrict__ src,
                            const int* __restrict__ dst,
                            int* deg_in, int* deg_out) {
    int i = blockIdx.x * blockDim.x + threadIdx.x;
    if (i < e) {
        atomicAdd(&deg_out[src[i]], 1);
        atomicAdd(&deg_in[dst[i]], 1);
    }
}

// Single-block exclusive scan (chunked, shfl-based).
__global__ void scan_kernel(int n, const int* __restrict__ deg, int* __restrict__ row_ptr) {
    __shared__ int wsum[32];
    __shared__ int s_carry;
    const int tid = threadIdx.x;
    const int lane = tid & 31;
    const int wid = tid >> 5;
    if (tid == 0) s_carry = 0;
    __syncthreads();
    for (int base = 0; base < n; base += 1024) {
        int idx = base + tid;
        int v = (idx < n) ? deg[idx] : 0;
        int x = v;
        #pragma unroll
        for (int o = 1; o < 32; o <<= 1) {
            int t = __shfl_up_sync(0xffffffffu, x, o);
            if (lane >= o) x += t;
        }
        if (lane == 31) wsum[wid] = x;
        __syncthreads();
        if (wid == 0) {
            int y = wsum[lane];
            #pragma unroll
            for (int o = 1; o < 32; o <<= 1) {
                int t = __shfl_up_sync(0xffffffffu, y, o);
                if (lane >= o) y += t;
            }
            wsum[lane] = y;
        }
        __syncthreads();
        int wofs = (wid > 0) ? wsum[wid - 1] : 0;
        int incl = x + wofs;
        int carry = s_carry;
        if (idx < n) row_ptr[idx] = carry + incl - v;  // exclusive
        __syncthreads();
        if (tid == 1023) s_carry = carry + wsum[31];
        __syncthreads();
    }
    if (threadIdx.x == 0) row_ptr[n] = s_carry;
}

__global__ void finalize_kernel(int n, const int* __restrict__ deg_out,
                                const int* __restrict__ deg_in,
                                const int* __restrict__ row_ptr,
                                float* out_norm, float* in_norm, int* cursor) {
    int i = blockIdx.x * blockDim.x + threadIdx.x;
    if (i < n) {
        out_norm[i] = rsqrtf((float)max(deg_out[i], 1));
        in_norm[i]  = rsqrtf((float)max(deg_in[i], 1));
        cursor[i]   = row_ptr[i];
    }
}

__global__ void scatter_kernel(int e, const int* __restrict__ src,
                               const int* __restrict__ dst,
                               int* cursor, int* __restrict__ sorted_src) {
    int i = blockIdx.x * blockDim.x + threadIdx.x;
    if (i < e) {
        int d = dst[i];
        int pos = atomicAdd(&cursor[d], 1);
        sorted_src[pos] = src[i];
    }
}

// xh[i, :] = fp16(x[i, :] * out_norm[i]); one thread per 4 features.
__global__ void convert_x_kernel(int n, const float* __restrict__ x,
                                 const float* __restrict__ onorm,
                                 __half* __restrict__ xh) {
    int idx = blockIdx.x * blockDim.x + threadIdx.x;   // 0 .. n*32-1
    if (idx >= n * 32) return;
    int row = idx >> 5;
    float s = onorm[row];
    float4 v = *reinterpret_cast<const float4*>(x + (size_t)idx * 4);
    __half2 o0 = __floats2half2_rn(v.x * s, v.y * s);
    __half2 o1 = __floats2half2_rn(v.z * s, v.w * s);
    uint2 ov;
    ov.x = *reinterpret_cast<uint32_t*>(&o0);
    ov.y = *reinterpret_cast<uint32_t*>(&o1);
    *reinterpret_cast<uint2*>(xh + (size_t)idx * 4) = ov;
}

// ---------------------------------------------------------------------------
// Aggregation: one warp per node; lane l owns features [4l, 4l+4).
// Reads fp16 rows (prescaled by out_norm), accumulates fp32,
// writes fp32 * in_norm. Main loop unrolled 4-wide for MLP.
__global__ void agg_h2f_kernel(int n, const __half* __restrict__ feat,
                               const int* __restrict__ row_ptr,
                               const int* __restrict__ srcs,
                               const float* __restrict__ inorm,
                               float* __restrict__ out) {
    int warp = (blockIdx.x * blockDim.x + threadIdx.x) >> 5;
    if (warp >= n) return;
    const int lane = threadIdx.x & 31;
    const int beg = row_ptr[warp];
    const int end = row_ptr[warp + 1];
    float a0 = 0.f, a1 = 0.f, a2 = 0.f, a3 = 0.f;

    auto acc8 = [&](uint2 v) {
        __half2 h0 = *reinterpret_cast<__half2*>(&v.x);
        __half2 h1 = *reinterpret_cast<__half2*>(&v.y);
        float2 f0 = __half22float2(h0);
        float2 f1 = __half22float2(h1);
        a0 += f0.x; a1 += f0.y; a2 += f1.x; a3 += f1.y;
    };

    int i = beg;
    for (; i + 32 <= end; i += 32) {
        int s = __ldg(srcs + i + lane);
        #pragma unroll
        for (int j = 0; j < 32; j += 4) {
            int s0 = __shfl_sync(0xffffffffu, s, j + 0);
            int s1 = __shfl_sync(0xffffffffu, s, j + 1);
            int s2 = __shfl_sync(0xffffffffu, s, j + 2);
            int s3 = __shfl_sync(0xffffffffu, s, j + 3);
            uint2 v0 = *reinterpret_cast<const uint2*>(feat + (size_t)s0 * 128 + lane * 4);
            uint2 v1 = *reinterpret_cast<const uint2*>(feat + (size_t)s1 * 128 + lane * 4);
            uint2 v2 = *reinterpret_cast<const uint2*>(feat + (size_t)s2 * 128 + lane * 4);
            uint2 v3 = *reinterpret_cast<const uint2*>(feat + (size_t)s3 * 128 + lane * 4);
            acc8(v0); acc8(v1); acc8(v2); acc8(v3);
        }
    }
    if (i < end) {
        int cnt = end - i;
        int s = 0;
        if (lane < cnt) s = __ldg(srcs + i + lane);
        for (int j = 0; j < cnt; j++) {
            int sj = __shfl_sync(0xffffffffu, s, j);
            uint2 v = *reinterpret_cast<const uint2*>(feat + (size_t)sj * 128 + lane * 4);
            acc8(v);
        }
    }
    float iw = inorm[warp];
    float4 o = make_float4(a0 * iw, a1 * iw, a2 * iw, a3 * iw);
    *reinterpret_cast<float4*>(out + (size_t)warp * 128 + lane * 4) = o;
}

// ---------------------------------------------------------------------------
// tf32 tensor-core GEMM via mma.sync.m16n8k8 (identical to R3 except the
// optional fp16 output path). Block 128x64x32, 8 warps = 4(M) x 2(N).
// ---------------------------------------------------------------------------
__device__ __forceinline__ uint32_t f2tf32(float x) {
    uint32_t r;
    asm("cvt.rna.tf32.f32 %0, %1;" : "=r"(r) : "f"(x));
    return r;
}

__device__ __forceinline__ void mma_tf32(float c[4], uint32_t a0, uint32_t a1,
                                         uint32_t a2, uint32_t a3,
                                         uint32_t b0, uint32_t b1) {
    asm volatile(
        "mma.sync.aligned.m16n8k8.row.col.f32.tf32.tf32.f32 "
        "{%0,%1,%2,%3}, {%4,%5,%6,%7}, {%8,%9}, {%0,%1,%2,%3};\n"
        : "+f"(c[0]), "+f"(c[1]), "+f"(c[2]), "+f"(c[3])
        : "r"(a0), "r"(a1), "r"(a2), "r"(a3), "r"(b0), "r"(b1));
}

template <bool RELU, bool PSCALE, bool OUTH>
__global__ __launch_bounds__(256) void gemm_tf32_kernel(
        int M, int K, int ldn,
        const float* __restrict__ A,
        const float* __restrict__ W,
        const float* __restrict__ bias,
        const float* __restrict__ pscale,
        void* __restrict__ Cout) {
    constexpr int BM = 128, BN = 64, BK = 32;
    constexpr int ASTR = BK + 4;   // 36 words
    constexpr int WSTR = BN + 4;   // 68 words
    __shared__ uint32_t As[BM * ASTR];
    __shared__ uint32_t Ws[BK * WSTR];

    const int tid = threadIdx.x;
    const int lane = tid & 31;
    const int wid = tid >> 5;
    const int g = lane >> 2;
    const int tig = lane & 3;
    const int warpM = (wid & 3) * 32;
    const int warpN = (wid >> 2) * 32;
    const int rowBase = blockIdx.x * BM;
    const int nBase = blockIdx.y * BN;

    float4 ra[4];
    float4 rw[2];

    auto loadA = [&](int kb) {
        #pragma unroll
        for (int i = 0; i < 4; i++) {
            int id = tid + i * 256;
            int row = id >> 3;
            int c4 = (id & 7) * 4;
            int grow = rowBase + row;
            if (grow < M)
                ra[i] = *reinterpret_cast<const float4*>(A + (size_t)grow * K + kb + c4);
            else
                ra[i] = make_float4(0.f, 0.f, 0.f, 0.f);
        }
    };
    auto loadW = [&](int kb) {
        #pragma unroll
        for (int i = 0; i < 2; i++) {
            int id = tid + i * 256;
            int row = id >> 4;
            int c4 = (id & 15) * 4;
            rw[i] = *reinterpret_cast<const float4*>(W + (size_t)(kb + row) * ldn + nBase + c4);
        }
    };
    auto storeA = [&]() {
        #pragma unroll
        for (int i = 0; i < 4; i++) {
            int id = tid + i * 256;
            int row = id >> 3;
            int c4 = (id & 7) * 4;
            uint32_t* p = &As[row * ASTR + c4];
            p[0] = f2tf32(ra[i].x);
            p[1] = f2tf32(ra[i].y);
            p[2] = f2tf32(ra[i].z);
            p[3] = f2tf32(ra[i].w);
        }
    };
    auto storeW = [&]() {
        #pragma unroll
        for (int i = 0; i < 2; i++) {
            int id = tid + i * 256;
            int row = id >> 4;
            int c4 = (id & 15) * 4;
            uint32_t* p = &Ws[row * WSTR + c4];
            p[0] = f2tf32(rw[i].x);
            p[1] = f2tf32(rw[i].y);
            p[2] = f2tf32(rw[i].z);
            p[3] = f2tf32(rw[i].w);
        }
    };

    float acc[2][4][4];
    #pragma unroll
    for (int m = 0; m < 2; m++)
        #pragma unroll
        for (int n = 0; n < 4; n++)
            #pragma unroll
            for (int q = 0; q < 4; q++) acc[m][n][q] = 0.f;

    loadA(0);
    loadW(0);

    for (int kb = 0; kb < K; kb += BK) {
        storeA();
        storeW();
        __syncthreads();
        if (kb + BK < K) { loadA(kb + BK); loadW(kb + BK); }

        #pragma unroll
        for (int ks = 0; ks < BK; ks += 8) {
            uint32_t af[2][4];
            #pragma unroll
            for (int m = 0; m < 2; m++) {
                int r0 = warpM + m * 16 + g;
                int r1 = r0 + 8;
                af[m][0] = As[r0 * ASTR + ks + tig];
                af[m][1] = As[r1 * ASTR + ks + tig];
                af[m][2] = As[r0 * ASTR + ks + tig + 4];
                af[m][3] = As[r1 * ASTR + ks + tig + 4];
            }
            uint32_t bf[4][2];
            #pragma unroll
            for (int n = 0; n < 4; n++) {
                int cn = warpN + n * 8 + g;
                bf[n][0] = Ws[(ks + tig) * WSTR + cn];
                bf[n][1] = Ws[(ks + tig + 4) * WSTR + cn];
            }
            #pragma unroll
            for (int m = 0; m < 2; m++)
                #pragma unroll
                for (int n = 0; n < 4; n++)
                    mma_tf32(acc[m][n], af[m][0], af[m][1], af[m][2], af[m][3],
                             bf[n][0], bf[n][1]);
        }
        __syncthreads();
    }

    #pragma unroll
    for (int n = 0; n < 4; n++) {
        int col = nBase + warpN + n * 8 + tig * 2;
        float bv0 = bias[col];
        float bv1 = bias[col + 1];
        #pragma unroll
        for (int m = 0; m < 2; m++) {
            #pragma unroll
            for (int hf = 0; hf < 2; hf++) {
                int row = rowBase + warpM + m * 16 + g + hf * 8;
                if (row >= M) continue;
                float sc = PSCALE ? pscale[row] : 1.f;
                float o0 = acc[m][n][hf * 2 + 0] + bv0;
                float o1 = acc[m][n][hf * 2 + 1] + bv1;
                if (RELU) { o0 = fmaxf(o0, 0.f); o1 = fmaxf(o1, 0.f); }
                o0 *= sc; o1 *= sc;
                if (OUTH) {
                    __half2 o = __floats2half2_rn(o0, o1);
                    *reinterpret_cast<__half2*>((__half*)Cout + (size_t)row * ldn + col) = o;
                } else {
                    *reinterpret_cast<float2*>((float*)Cout + (size_t)row * ldn + col) =
                        make_float2(o0, o1);
                }
            }
        }
    }
}

// ---------------------------------------------------------------------------
extern "C" void kernel_launch(void* const* d_in, const int* in_sizes, int n_in,
                              void* d_out, int out_size) {
    const float* x   = (const float*)d_in[0];
    const int*   src = (const int*)d_in[1];
    const int*   dst = (const int*)d_in[2];
    const float* w1  = (const float*)d_in[3];
    const float* b1  = (const float*)d_in[4];
    const float* w2  = (const float*)d_in[5];
    const float* b2  = (const float*)d_in[6];
    const float* wm1 = (const float*)d_in[7];
    const float* bm1 = (const float*)d_in[8];
    const float* wm2 = (const float*)d_in[9];
    const float* bm2 = (const float*)d_in[10];

    const int n = in_sizes[0] / 128;
    const int e = in_sizes[1];

    int *deg_in, *deg_out, *row_ptr, *cursor, *sorted_src;
    float *onorm, *inorm, *aggf, *h, *h3;
    __half *xh, *h1h;
    cudaGetSymbolAddress((void**)&deg_in, g_deg_in);
    cudaGetSymbolAddress((void**)&deg_out, g_deg_out);
    cudaGetSymbolAddress((void**)&row_ptr, g_row_ptr);
    cudaGetSymbolAddress((void**)&cursor, g_cursor);
    cudaGetSymbolAddress((void**)&sorted_src, g_sorted_src);
    cudaGetSymbolAddress((void**)&onorm, g_out_norm);
    cudaGetSymbolAddress((void**)&inorm, g_in_norm);
    cudaGetSymbolAddress((void**)&xh, g_xh);
    cudaGetSymbolAddress((void**)&h1h, g_h1h);
    cudaGetSymbolAddress((void**)&aggf, g_aggf);
    cudaGetSymbolAddress((void**)&h, g_h);
    cudaGetSymbolAddress((void**)&h3, g_h3);

    const int nb = (n + 255) / 256;
    const int eb = (e + 255) / 256;

    // --- CSR build ---
    zero_deg_kernel<<<nb, 256>>>(n, deg_in, deg_out);
    hist_kernel<<<eb, 256>>>(e, src, dst, deg_in, deg_out);
    scan_kernel<<<1, 1024>>>(n, deg_in, row_ptr);
    finalize_kernel<<<nb, 256>>>(n, deg_out, deg_in, row_ptr, onorm, inorm, cursor);
    scatter_kernel<<<eb, 256>>>(e, src, dst, cursor, sorted_src);

    // --- x -> fp16 prescaled by out_norm ---
    convert_x_kernel<<<(n * 32 + 255) / 256, 256>>>(n, x, onorm, xh);

    const int aggBlocks = (n + 7) / 8;
    const dim3 g2((n + 127) / 128, 2);
    const dim3 g4((n + 127) / 128, 4);
    const dim3 g1((n + 127) / 128, 1);

    // --- conv1: agg fp16 -> fp32, tf32 GEMM, epilogue writes fp16*onorm ---
    agg_h2f_kernel<<<aggBlocks, 256>>>(n, xh, row_ptr, sorted_src, inorm, aggf);
    gemm_tf32_kernel<true, true, true><<<g2, 256>>>(n, 128, 128, aggf, w1, b1, onorm, h1h);

    // --- conv2: agg fp16 -> fp32, tf32 GEMM, fp32 out ---
    agg_h2f_kernel<<<aggBlocks, 256>>>(n, h1h, row_ptr, sorted_src, inorm, aggf);
    gemm_tf32_kernel<true, false, false><<<g2, 256>>>(n, 128, 128, aggf, w2, b2, nullptr, h);

    // --- MLP ---
    gemm_tf32_kernel<true, false, false><<<g4, 256>>>(n, 128, 256, h, wm1, bm1, nullptr, h3);
    gemm_tf32_kernel<false, false, false><<<g1, 256>>>(n, 256, 64, h3, wm2, bm2, nullptr, d_out);
}

// round 7
// speedup vs baseline: 1.3290x; 1.3290x over previous
#include <cuda_runtime.h>
#include <cstdint>

// ---------------------------------------------------------------------------
// GCN (all-fp32 gather path, tf32 tensor-core GEMMs):
//   xs   = x * out_norm                     [prescale, fp32]
//   agg1 = Agg(xs) * in_norm                [gather-only, fp32]
//   h1s  = relu(agg1 @ w1 + b1) * out_norm  [tf32 GEMM, fused epilogue]
//   agg2 = Agg(h1s) * in_norm
//   h2   = relu(agg2 @ w2 + b2)
//   h3   = relu(h2 @ wm1 + bm1)
//   out  = h3 @ wm2 + bm2
// CSR built per-launch: histogram -> single-block scan -> bucket scatter.
// ---------------------------------------------------------------------------

#define N_MAX 100000
#define E_MAX 3200000

__device__ int   g_deg_in[N_MAX];
__device__ int   g_deg_out[N_MAX];
__device__ int   g_row_ptr[N_MAX + 1];
__device__ int   g_cursor[N_MAX];
__device__ int   g_sorted_src[E_MAX];
__device__ float g_out_norm[N_MAX];
__device__ float g_in_norm[N_MAX];
__device__ float g_xs[(size_t)N_MAX * 128];   // prescaled gather features
__device__ float g_agg[(size_t)N_MAX * 128];  // agg output (GEMM A input)
__device__ float g_h[(size_t)N_MAX * 128];    // h1s, then h2
__device__ float g_h3[(size_t)N_MAX * 256];   // MLP hidden

// ---------------------------------------------------------------------------
__global__ void zero_deg_kernel(int n, int* deg_in, int* deg_out) {
    int i = blockIdx.x * blockDim.x + threadIdx.x;
    if (i < n) { deg_in[i] = 0; deg_out[i] = 0; }
}

__global__ void hist_kernel(int e, const int* __restrict__ src,
                            const int* __restrict__ dst,
                            int* deg_in, int* deg_out) {
    int i = blockIdx.x * blockDim.x + threadIdx.x;
    if (i < e) {
        atomicAdd(&deg_out[src[i]], 1);
        atomicAdd(&deg_in[dst[i]], 1);
    }
}

// Single-block exclusive scan, 4 elements per thread per chunk (4096/chunk).
__global__ void scan_kernel(int n, const int* __restrict__ deg, int* __restrict__ row_ptr) {
    __shared__ int wsum[32];
    __shared__ int s_carry;
    const int tid = threadIdx.x;
    const int lane = tid & 31;
    const int wid = tid >> 5;
    if (tid == 0) s_carry = 0;
    __syncthreads();
    for (int base = 0; base < n; base += 4096) {
        int i0 = base + tid * 4;
        int v0 = (i0 + 0 < n) ? deg[i0 + 0] : 0;
        int v1 = (i0 + 1 < n) ? deg[i0 + 1] : 0;
        int v2 = (i0 + 2 < n) ? deg[i0 + 2] : 0;
        int v3 = (i0 + 3 < n) ? deg[i0 + 3] : 0;
        int t = v0 + v1 + v2 + v3;
        // warp inclusive scan of per-thread sums
        int x = t;
        #pragma unroll
        for (int o = 1; o < 32; o <<= 1) {
            int u = __shfl_up_sync(0xffffffffu, x, o);
            if (lane >= o) x += u;
        }
        if (lane == 31) wsum[wid] = x;
        __syncthreads();
        if (wid == 0) {
            int y = wsum[lane];
            #pragma unroll
            for (int o = 1; o < 32; o <<= 1) {
                int u = __shfl_up_sync(0xffffffffu, y, o);
                if (lane >= o) y += u;
            }
            wsum[lane] = y;
        }
        __syncthreads();
        int wofs = (wid > 0) ? wsum[wid - 1] : 0;
        int carry = s_carry;
        int excl = carry + wofs + (x - t);   // exclusive prefix of this thread's chunk
        if (i0 + 0 < n) row_ptr[i0 + 0] = excl;
        if (i0 + 1 < n) row_ptr[i0 + 1] = excl + v0;
        if (i0 + 2 < n) row_ptr[i0 + 2] = excl + v0 + v1;
        if (i0 + 3 < n) row_ptr[i0 + 3] = excl + v0 + v1 + v2;
        __syncthreads();
        if (tid == 1023) s_carry = carry + wsum[31];
        __syncthreads();
    }
    if (threadIdx.x == 0) row_ptr[n] = s_carry;
}

__global__ void finalize_kernel(int n, const int* __restrict__ deg_out,
                                const int* __restrict__ deg_in,
                                const int* __restrict__ row_ptr,
                                float* out_norm, float* in_norm, int* cursor) {
    int i = blockIdx.x * blockDim.x + threadIdx.x;
    if (i < n) {
        out_norm[i] = rsqrtf((float)max(deg_out[i], 1));
        in_norm[i]  = rsqrtf((float)max(deg_in[i], 1));
        cursor[i]   = row_ptr[i];
    }
}

__global__ void scatter_kernel(int e, const int* __restrict__ src,
                               const int* __restrict__ dst,
                               int* cursor, int* __restrict__ sorted_src) {
    int i = blockIdx.x * blockDim.x + threadIdx.x;
    if (i < e) {
        int d = dst[i];
        int pos = atomicAdd(&cursor[d], 1);
        sorted_src[pos] = src[i];
    }
}

// xs[i, :] = x[i, :] * out_norm[i]; one thread per 4 features (fp32).
__global__ void prescale_x_kernel(int n, const float* __restrict__ x,
                                  const float* __restrict__ onorm,
                                  float* __restrict__ xs) {
    int idx = blockIdx.x * blockDim.x + threadIdx.x;   // 0 .. n*32-1
    if (idx >= n * 32) return;
    int row = idx >> 5;
    float s = onorm[row];
    float4 v = *reinterpret_cast<const float4*>(x + (size_t)idx * 4);
    v.x *= s; v.y *= s; v.z *= s; v.w *= s;
    *reinterpret_cast<float4*>(xs + (size_t)idx * 4) = v;
}

// ---------------------------------------------------------------------------
// Aggregation: one warp per node; lane l owns features [4l, 4l+4).
// Source rows already prescaled by out_norm. fp32 accumulate, output *in_norm.
// 4-wide unrolled with two accumulator sets.
__global__ void agg_kernel(int n, const float* __restrict__ feat,
                           const int* __restrict__ row_ptr,
                           const int* __restrict__ srcs,
                           const float* __restrict__ inorm,
                           float* __restrict__ out) {
    int warp = (blockIdx.x * blockDim.x + threadIdx.x) >> 5;
    if (warp >= n) return;
    const int lane = threadIdx.x & 31;
    const int beg = row_ptr[warp];
    const int end = row_ptr[warp + 1];
    const float* fl = feat + lane * 4;

    float4 accA = make_float4(0.f, 0.f, 0.f, 0.f);
    float4 accB = make_float4(0.f, 0.f, 0.f, 0.f);

    int i = beg;
    for (; i + 32 <= end; i += 32) {
        int s = __ldg(srcs + i + lane);
        #pragma unroll
        for (int j = 0; j < 32; j += 4) {
            int s0 = __shfl_sync(0xffffffffu, s, j + 0);
            int s1 = __shfl_sync(0xffffffffu, s, j + 1);
            int s2 = __shfl_sync(0xffffffffu, s, j + 2);
            int s3 = __shfl_sync(0xffffffffu, s, j + 3);
            float4 v0 = *reinterpret_cast<const float4*>(fl + (size_t)s0 * 128);
            float4 v1 = *reinterpret_cast<const float4*>(fl + (size_t)s1 * 128);
            float4 v2 = *reinterpret_cast<const float4*>(fl + (size_t)s2 * 128);
            float4 v3 = *reinterpret_cast<const float4*>(fl + (size_t)s3 * 128);
            accA.x += v0.x; accA.y += v0.y; accA.z += v0.z; accA.w += v0.w;
            accB.x += v1.x; accB.y += v1.y; accB.z += v1.z; accB.w += v1.w;
            accA.x += v2.x; accA.y += v2.y; accA.z += v2.z; accA.w += v2.w;
            accB.x += v3.x; accB.y += v3.y; accB.z += v3.z; accB.w += v3.w;
        }
    }
    if (i < end) {
        int cnt = end - i;
        int s = 0;
        if (lane < cnt) s = __ldg(srcs + i + lane);
        for (int j = 0; j < cnt; j++) {
            int sj = __shfl_sync(0xffffffffu, s, j);
            float4 v = *reinterpret_cast<const float4*>(fl + (size_t)sj * 128);
            accA.x += v.x; accA.y += v.y; accA.z += v.z; accA.w += v.w;
        }
    }
    float iw = inorm[warp];
    float4 o = make_float4((accA.x + accB.x) * iw, (accA.y + accB.y) * iw,
                           (accA.z + accB.z) * iw, (accA.w + accB.w) * iw);
    *reinterpret_cast<float4*>(out + (size_t)warp * 128 + lane * 4) = o;
}

// ---------------------------------------------------------------------------
// tf32 tensor-core GEMM via mma.sync.m16n8k8 (proven R3 kernel).
// Block 128x64x32, 8 warps = 4(M) x 2(N), warp tile 32x32.
// ---------------------------------------------------------------------------
__device__ __forceinline__ uint32_t f2tf32(float x) {
    uint32_t r;
    asm("cvt.rna.tf32.f32 %0, %1;" : "=r"(r) : "f"(x));
    return r;
}

__device__ __forceinline__ void mma_tf32(float c[4], uint32_t a0, uint32_t a1,
                                         uint32_t a2, uint32_t a3,
                                         uint32_t b0, uint32_t b1) {
    asm volatile(
        "mma.sync.aligned.m16n8k8.row.col.f32.tf32.tf32.f32 "
        "{%0,%1,%2,%3}, {%4,%5,%6,%7}, {%8,%9}, {%0,%1,%2,%3};\n"
        : "+f"(c[0]), "+f"(c[1]), "+f"(c[2]), "+f"(c[3])
        : "r"(a0), "r"(a1), "r"(a2), "r"(a3), "r"(b0), "r"(b1));
}

template <bool RELU, bool PSCALE>
__global__ __launch_bounds__(256) void gemm_tf32_kernel(
        int M, int K, int ldn,
        const float* __restrict__ A,
        const float* __restrict__ W,
        const float* __restrict__ bias,
        const float* __restrict__ pscale,
        float* __restrict__ C) {
    constexpr int BM = 128, BN = 64, BK = 32;
    constexpr int ASTR = BK + 4;   // 36 words
    constexpr int WSTR = BN + 4;   // 68 words
    __shared__ uint32_t As[BM * ASTR];
    __shared__ uint32_t Ws[BK * WSTR];

    const int tid = threadIdx.x;
    const int lane = tid & 31;
    const int wid = tid >> 5;
    const int g = lane >> 2;
    const int tig = lane & 3;
    const int warpM = (wid & 3) * 32;
    const int warpN = (wid >> 2) * 32;
    const int rowBase = blockIdx.x * BM;
    const int nBase = blockIdx.y * BN;

    float4 ra[4];
    float4 rw[2];

    auto loadA = [&](int kb) {
        #pragma unroll
        for (int i = 0; i < 4; i++) {
            int id = tid + i * 256;
            int row = id >> 3;
            int c4 = (id & 7) * 4;
            int grow = rowBase + row;
            if (grow < M)
                ra[i] = *reinterpret_cast<const float4*>(A + (size_t)grow * K + kb + c4);
            else
                ra[i] = make_float4(0.f, 0.f, 0.f, 0.f);
        }
    };
    auto loadW = [&](int kb) {
        #pragma unroll
        for (int i = 0; i < 2; i++) {
            int id = tid + i * 256;
            int row = id >> 4;
            int c4 = (id & 15) * 4;
            rw[i] = *reinterpret_cast<const float4*>(W + (size_t)(kb + row) * ldn + nBase + c4);
        }
    };
    auto storeA = [&]() {
        #pragma unroll
        for (int i = 0; i < 4; i++) {
            int id = tid + i * 256;
            int row = id >> 3;
            int c4 = (id & 7) * 4;
            uint32_t* p = &As[row * ASTR + c4];
            p[0] = f2tf32(ra[i].x);
            p[1] = f2tf32(ra[i].y);
            p[2] = f2tf32(ra[i].z);
            p[3] = f2tf32(ra[i].w);
        }
    };
    auto storeW = [&]() {
        #pragma unroll
        for (int i = 0; i < 2; i++) {
            int id = tid + i * 256;
            int row = id >> 4;
            int c4 = (id & 15) * 4;
            uint32_t* p = &Ws[row * WSTR + c4];
            p[0] = f2tf32(rw[i].x);
            p[1] = f2tf32(rw[i].y);
            p[2] = f2tf32(rw[i].z);
            p[3] = f2tf32(rw[i].w);
        }
    };

    float acc[2][4][4];
    #pragma unroll
    for (int m = 0; m < 2; m++)
        #pragma unroll
        for (int n = 0; n < 4; n++)
            #pragma unroll
            for (int q = 0; q < 4; q++) acc[m][n][q] = 0.f;

    loadA(0);
    loadW(0);

    for (int kb = 0; kb < K; kb += BK) {
        storeA();
        storeW();
        __syncthreads();
        if (kb + BK < K) { loadA(kb + BK); loadW(kb + BK); }

        #pragma unroll
        for (int ks = 0; ks < BK; ks += 8) {
            uint32_t af[2][4];
            #pragma unroll
            for (int m = 0; m < 2; m++) {
                int r0 = warpM + m * 16 + g;
                int r1 = r0 + 8;
                af[m][0] = As[r0 * ASTR + ks + tig];
                af[m][1] = As[r1 * ASTR + ks + tig];
                af[m][2] = As[r0 * ASTR + ks + tig + 4];
                af[m][3] = As[r1 * ASTR + ks + tig + 4];
            }
            uint32_t bf[4][2];
            #pragma unroll
            for (int n = 0; n < 4; n++) {
                int cn = warpN + n * 8 + g;
                bf[n][0] = Ws[(ks + tig) * WSTR + cn];
                bf[n][1] = Ws[(ks + tig + 4) * WSTR + cn];
            }
            #pragma unroll
            for (int m = 0; m < 2; m++)
                #pragma unroll
                for (int n = 0; n < 4; n++)
                    mma_tf32(acc[m][n], af[m][0], af[m][1], af[m][2], af[m][3],
                             bf[n][0], bf[n][1]);
        }
        __syncthreads();
    }

    #pragma unroll
    for (int n = 0; n < 4; n++) {
        int col = nBase + warpN + n * 8 + tig * 2;
        float bv0 = bias[col];
        float bv1 = bias[col + 1];
        #pragma unroll
        for (int m = 0; m < 2; m++) {
            #pragma unroll
            for (int hf = 0; hf < 2; hf++) {
                int row = rowBase + warpM + m * 16 + g + hf * 8;
                if (row >= M) continue;
                float sc = PSCALE ? pscale[row] : 1.f;
                float o0 = acc[m][n][hf * 2 + 0] + bv0;
                float o1 = acc[m][n][hf * 2 + 1] + bv1;
                if (RELU) { o0 = fmaxf(o0, 0.f); o1 = fmaxf(o1, 0.f); }
                *reinterpret_cast<float2*>(C + (size_t)row * ldn + col) =
                    make_float2(o0 * sc, o1 * sc);
            }
        }
    }
}

// ---------------------------------------------------------------------------
extern "C" void kernel_launch(void* const* d_in, const int* in_sizes, int n_in,
                              void* d_out, int out_size) {
    const float* x   = (const float*)d_in[0];
    const int*   src = (const int*)d_in[1];
    const int*   dst = (const int*)d_in[2];
    const float* w1  = (const float*)d_in[3];
    const float* b1  = (const float*)d_in[4];
    const float* w2  = (const float*)d_in[5];
    const float* b2  = (const float*)d_in[6];
    const float* wm1 = (const float*)d_in[7];
    const float* bm1 = (const float*)d_in[8];
    const float* wm2 = (const float*)d_in[9];
    const float* bm2 = (const float*)d_in[10];

    const int n = in_sizes[0] / 128;
    const int e = in_sizes[1];

    int *deg_in, *deg_out, *row_ptr, *cursor, *sorted_src;
    float *onorm, *inorm, *xs, *agg, *h, *h3;
    cudaGetSymbolAddress((void**)&deg_in, g_deg_in);
    cudaGetSymbolAddress((void**)&deg_out, g_deg_out);
    cudaGetSymbolAddress((void**)&row_ptr, g_row_ptr);
    cudaGetSymbolAddress((void**)&cursor, g_cursor);
    cudaGetSymbolAddress((void**)&sorted_src, g_sorted_src);
    cudaGetSymbolAddress((void**)&onorm, g_out_norm);
    cudaGetSymbolAddress((void**)&inorm, g_in_norm);
    cudaGetSymbolAddress((void**)&xs, g_xs);
    cudaGetSymbolAddress((void**)&agg, g_agg);
    cudaGetSymbolAddress((void**)&h, g_h);
    cudaGetSymbolAddress((void**)&h3, g_h3);

    const int nb = (n + 255) / 256;
    const int eb = (e + 511) / 512;

    // --- CSR build ---
    zero_deg_kernel<<<nb, 256>>>(n, deg_in, deg_out);
    hist_kernel<<<eb, 512>>>(e, src, dst, deg_in, deg_out);
    scan_kernel<<<1, 1024>>>(n, deg_in, row_ptr);
    finalize_kernel<<<nb, 256>>>(n, deg_out, deg_in, row_ptr, onorm, inorm, cursor);
    scatter_kernel<<<eb, 512>>>(e, src, dst, cursor, sorted_src);

    // --- prescale x by out_norm (fp32) ---
    prescale_x_kernel<<<(n * 32 + 255) / 256, 256>>>(n, x, onorm, xs);

    const int aggBlocks = (n + 7) / 8;
    const dim3 g2((n + 127) / 128, 2);
    const dim3 g4((n + 127) / 128, 4);
    const dim3 g1((n + 127) / 128, 1);

    // --- conv1: agg(xs) * in_norm @ w1 + b1, relu, * out_norm ---
    agg_kernel<<<aggBlocks, 256>>>(n, xs, row_ptr, sorted_src, inorm, agg);
    gemm_tf32_kernel<true, true><<<g2, 256>>>(n, 128, 128, agg, w1, b1, onorm, h);

    // --- conv2: agg(h1s) * in_norm @ w2 + b2, relu ---
    agg_kernel<<<aggBlocks, 256>>>(n, h, row_ptr, sorted_src, inorm, agg);
    gemm_tf32_kernel<true, false><<<g2, 256>>>(n, 128, 128, agg, w2, b2, nullptr, h);

    // --- MLP ---
    gemm_tf32_kernel<true, false><<<g4, 256>>>(n, 128, 256, h, wm1, bm1, nullptr, h3);
    gemm_tf32_kernel<false, false><<<g1, 256>>>(n, 256, 64, h3, wm2, bm2, nullptr, (float*)d_out);
}

// round 8
// speedup vs baseline: 1.5075x; 1.1344x over previous
#include <cuda_runtime.h>
#include <cuda_fp16.h>
#include <cstdint>

// ---------------------------------------------------------------------------
// GCN: fp16 feature gather with pairwise HADD2 (conversion-amortized),
// fp32 accumulation, tf32 tensor-core GEMMs.
//   xh   = fp16(x * out_norm)                      [convert]
//   agg1 = fp32(pairsum_h(xh)) * in_norm           [fp16 gather, HADD2 pairs]
//   h1h  = fp16(relu(agg1 @ w1 + b1) * out_norm)   [tf32 GEMM epilogue]
//   agg2 = fp32(pairsum_h(h1h)) * in_norm
//   h2   = relu(agg2 @ w2 + b2)                    [fp32 out]
//   h3   = relu(h2 @ wm1 + bm1)
//   out  = h3 @ wm2 + bm2
// CSR built per-launch: histogram -> single-block scan -> bucket scatter.
// ---------------------------------------------------------------------------

#define N_MAX 100000
#define E_MAX 3200000

__device__ int    g_deg_in[N_MAX];
__device__ int    g_deg_out[N_MAX];
__device__ int    g_row_ptr[N_MAX + 1];
__device__ int    g_cursor[N_MAX];
__device__ int    g_sorted_src[E_MAX];
__device__ float  g_out_norm[N_MAX];
__device__ float  g_in_norm[N_MAX];
__device__ __half g_xh[(size_t)N_MAX * 128];   // pass-1 gather features (prescaled)
__device__ __half g_h1h[(size_t)N_MAX * 128];  // pass-2 gather features (prescaled)
__device__ float  g_agg[(size_t)N_MAX * 128];  // agg output (GEMM A input)
__device__ float  g_h[(size_t)N_MAX * 128];    // h2
__device__ float  g_h3[(size_t)N_MAX * 256];   // MLP hidden

// ---------------------------------------------------------------------------
__global__ void zero_deg_kernel(int n, int* deg_in, int* deg_out) {
    int i = blockIdx.x * blockDim.x + threadIdx.x;
    if (i < n) { deg_in[i] = 0; deg_out[i] = 0; }
}

__global__ void hist_kernel(int e, const int* __restrict__ src,
                            const int* __restrict__ dst,
                            int* deg_in, int* deg_out) {
    int i = blockIdx.x * blockDim.x + threadIdx.x;
    if (i < e) {
        atomicAdd(&deg_out[src[i]], 1);
        atomicAdd(&deg_in[dst[i]], 1);
    }
}

// Single-block exclusive scan, 4 elements per thread per chunk (4096/chunk).
__global__ void scan_kernel(int n, const int* __restrict__ deg, int* __restrict__ row_ptr) {
    __shared__ int wsum[32];
    __shared__ int s_carry;
    const int tid = threadIdx.x;
    const int lane = tid & 31;
    const int wid = tid >> 5;
    if (tid == 0) s_carry = 0;
    __syncthreads();
    for (int base = 0; base < n; base += 4096) {
        int i0 = base + tid * 4;
        int v0 = (i0 + 0 < n) ? deg[i0 + 0] : 0;
        int v1 = (i0 + 1 < n) ? deg[i0 + 1] : 0;
        int v2 = (i0 + 2 < n) ? deg[i0 + 2] : 0;
        int v3 = (i0 + 3 < n) ? deg[i0 + 3] : 0;
        int t = v0 + v1 + v2 + v3;
        int x = t;
        #pragma unroll
        for (int o = 1; o < 32; o <<= 1) {
            int u = __shfl_up_sync(0xffffffffu, x, o);
            if (lane >= o) x += u;
        }
        if (lane == 31) wsum[wid] = x;
        __syncthreads();
        if (wid == 0) {
            int y = wsum[lane];
            #pragma unroll
            for (int o = 1; o < 32; o <<= 1) {
                int u = __shfl_up_sync(0xffffffffu, y, o);
                if (lane >= o) y += u;
            }
            wsum[lane] = y;
        }
        __syncthreads();
        int wofs = (wid > 0) ? wsum[wid - 1] : 0;
        int carry = s_carry;
        int excl = carry + wofs + (x - t);
        if (i0 + 0 < n) row_ptr[i0 + 0] = excl;
        if (i0 + 1 < n) row_ptr[i0 + 1] = excl + v0;
        if (i0 + 2 < n) row_ptr[i0 + 2] = excl + v0 + v1;
        if (i0 + 3 < n) row_ptr[i0 + 3] = excl + v0 + v1 + v2;
        __syncthreads();
        if (tid == 1023) s_carry = carry + wsum[31];
        __syncthreads();
    }
    if (threadIdx.x == 0) row_ptr[n] = s_carry;
}

__global__ void finalize_kernel(int n, const int* __restrict__ deg_out,
                                const int* __restrict__ deg_in,
                                const int* __restrict__ row_ptr,
                                float* out_norm, float* in_norm, int* cursor) {
    int i = blockIdx.x * blockDim.x + threadIdx.x;
    if (i < n) {
        out_norm[i] = rsqrtf((float)max(deg_out[i], 1));
        in_norm[i]  = rsqrtf((float)max(deg_in[i], 1));
        cursor[i]   = row_ptr[i];
    }
}

__global__ void scatter_kernel(int e, const int* __restrict__ src,
                               const int* __restrict__ dst,
                               int* cursor, int* __restrict__ sorted_src) {
    int i = blockIdx.x * blockDim.x + threadIdx.x;
    if (i < e) {
        int d = dst[i];
        int pos = atomicAdd(&cursor[d], 1);
        sorted_src[pos] = src[i];
    }
}

// xh[i, :] = fp16(x[i, :] * out_norm[i]); one thread per 4 features.
__global__ void convert_x_kernel(int n, const float* __restrict__ x,
                                 const float* __restrict__ onorm,
                                 __half* __restrict__ xh) {
    int idx = blockIdx.x * blockDim.x + threadIdx.x;   // 0 .. n*32-1
    if (idx >= n * 32) return;
    int row = idx >> 5;
    float s = onorm[row];
    float4 v = *reinterpret_cast<const float4*>(x + (size_t)idx * 4);
    __half2 o0 = __floats2half2_rn(v.x * s, v.y * s);
    __half2 o1 = __floats2half2_rn(v.z * s, v.w * s);
    uint2 ov;
    ov.x = *reinterpret_cast<uint32_t*>(&o0);
    ov.y = *reinterpret_cast<uint32_t*>(&o1);
    *reinterpret_cast<uint2*>(xh + (size_t)idx * 4) = ov;
}

// ---------------------------------------------------------------------------
__device__ __forceinline__ __half2 u2h(uint32_t u) {
    __half2 h;
    *reinterpret_cast<uint32_t*>(&h) = u;
    return h;
}

// fp16 gather aggregation with pairwise HADD2: one warp per node; lane l owns
// features [4l, 4l+4). Edges summed in pairs on the fp16 fma pipe; pair-sums
// converted to fp32 (2 F2F/edge instead of 4) and accumulated. out *= in_norm.
__global__ void agg_hpair_kernel(int n, const __half* __restrict__ feat,
                                 const int* __restrict__ row_ptr,
                                 const int* __restrict__ srcs,
                                 const float* __restrict__ inorm,
                                 float* __restrict__ out) {
    int warp = (blockIdx.x * blockDim.x + threadIdx.x) >> 5;
    if (warp >= n) return;
    const int lane = threadIdx.x & 31;
    const int beg = row_ptr[warp];
    const int end = row_ptr[warp + 1];
    const __half* fl = feat + lane * 4;

    float a0 = 0.f, a1 = 0.f, a2 = 0.f, a3 = 0.f;
    float b0 = 0.f, b1 = 0.f, b2 = 0.f, b3 = 0.f;

    int i = beg;
    for (; i + 32 <= end; i += 32) {
        int s = __ldg(srcs + i + lane);
        #pragma unroll
        for (int j = 0; j < 32; j += 4) {
            int s0 = __shfl_sync(0xffffffffu, s, j + 0);
            int s1 = __shfl_sync(0xffffffffu, s, j + 1);
            int s2 = __shfl_sync(0xffffffffu, s, j + 2);
            int s3 = __shfl_sync(0xffffffffu, s, j + 3);
            uint2 w0 = *reinterpret_cast<const uint2*>(fl + (size_t)s0 * 128);
            uint2 w1 = *reinterpret_cast<const uint2*>(fl + (size_t)s1 * 128);
            uint2 w2 = *reinterpret_cast<const uint2*>(fl + (size_t)s2 * 128);
            uint2 w3 = *reinterpret_cast<const uint2*>(fl + (size_t)s3 * 128);
            // pair sums in fp16 (full-rate HADD2)
            __half2 p0 = __hadd2(u2h(w0.x), u2h(w1.x));
            __half2 p1 = __hadd2(u2h(w0.y), u2h(w1.y));
            __half2 q0 = __hadd2(u2h(w2.x), u2h(w3.x));
            __half2 q1 = __hadd2(u2h(w2.y), u2h(w3.y));
            float2 f;
            f = __half22float2(p0); a0 += f.x; a1 += f.y;
            f = __half22float2(p1); a2 += f.x; a3 += f.y;
            f = __half22float2(q0); b0 += f.x; b1 += f.y;
            f = __half22float2(q1); b2 += f.x; b3 += f.y;
        }
    }
    if (i < end) {
        int cnt = end - i;
        int s = 0;
        if (lane < cnt) s = __ldg(srcs + i + lane);
        int j = 0;
        for (; j + 2 <= cnt; j += 2) {
            int s0 = __shfl_sync(0xffffffffu, s, j + 0);
            int s1 = __shfl_sync(0xffffffffu, s, j + 1);
            uint2 w0 = *reinterpret_cast<const uint2*>(fl + (size_t)s0 * 128);
            uint2 w1 = *reinterpret_cast<const uint2*>(fl + (size_t)s1 * 128);
            __half2 p0 = __hadd2(u2h(w0.x), u2h(w1.x));
            __half2 p1 = __hadd2(u2h(w0.y), u2h(w1.y));
            float2 f;
            f = __half22float2(p0); a0 += f.x; a1 += f.y;
            f = __half22float2(p1); a2 += f.x; a3 += f.y;
        }
        if (j < cnt) {
            int s0 = __shfl_sync(0xffffffffu, s, j);
            uint2 w0 = *reinterpret_cast<const uint2*>(fl + (size_t)s0 * 128);
            float2 f;
            f = __half22float2(u2h(w0.x)); a0 += f.x; a1 += f.y;
            f = __half22float2(u2h(w0.y)); a2 += f.x; a3 += f.y;
        }
    }
    float iw = inorm[warp];
    float4 o = make_float4((a0 + b0) * iw, (a1 + b1) * iw,
                           (a2 + b2) * iw, (a3 + b3) * iw);
    *reinterpret_cast<float4*>(out + (size_t)warp * 128 + lane * 4) = o;
}

// ---------------------------------------------------------------------------
// tf32 tensor-core GEMM via mma.sync.m16n8k8 (proven kernel).
// Block 128x64x32, 8 warps = 4(M) x 2(N), warp tile 32x32.
// Epilogue: +bias, optional relu, optional per-row scale, fp32 or fp16 out.
// ---------------------------------------------------------------------------
__device__ __forceinline__ uint32_t f2tf32(float x) {
    uint32_t r;
    asm("cvt.rna.tf32.f32 %0, %1;" : "=r"(r) : "f"(x));
    return r;
}

__device__ __forceinline__ void mma_tf32(float c[4], uint32_t a0, uint32_t a1,
                                         uint32_t a2, uint32_t a3,
                                         uint32_t b0, uint32_t b1) {
    asm volatile(
        "mma.sync.aligned.m16n8k8.row.col.f32.tf32.tf32.f32 "
        "{%0,%1,%2,%3}, {%4,%5,%6,%7}, {%8,%9}, {%0,%1,%2,%3};\n"
        : "+f"(c[0]), "+f"(c[1]), "+f"(c[2]), "+f"(c[3])
        : "r"(a0), "r"(a1), "r"(a2), "r"(a3), "r"(b0), "r"(b1));
}

template <bool RELU, bool PSCALE, bool OUTH>
__global__ __launch_bounds__(256) void gemm_tf32_kernel(
        int M, int K, int ldn,
        const float* __restrict__ A,
        const float* __restrict__ W,
        const float* __restrict__ bias,
        const float* __restrict__ pscale,
        void* __restrict__ Cout) {
    constexpr int BM = 128, BN = 64, BK = 32;
    constexpr int ASTR = BK + 4;   // 36 words
    constexpr int WSTR = BN + 4;   // 68 words
    __shared__ uint32_t As[BM * ASTR];
    __shared__ uint32_t Ws[BK * WSTR];

    const int tid = threadIdx.x;
    const int lane = tid & 31;
    const int wid = tid >> 5;
    const int g = lane >> 2;
    const int tig = lane & 3;
    const int warpM = (wid & 3) * 32;
    const int warpN = (wid >> 2) * 32;
    const int rowBase = blockIdx.x * BM;
    const int nBase = blockIdx.y * BN;

    float4 ra[4];
    float4 rw[2];

    auto loadA = [&](int kb) {
        #pragma unroll
        for (int i = 0; i < 4; i++) {
            int id = tid + i * 256;
            int row = id >> 3;
            int c4 = (id & 7) * 4;
            int grow = rowBase + row;
            if (grow < M)
                ra[i] = *reinterpret_cast<const float4*>(A + (size_t)grow * K + kb + c4);
            else
                ra[i] = make_float4(0.f, 0.f, 0.f, 0.f);
        }
    };
    auto loadW = [&](int kb) {
        #pragma unroll
        for (int i = 0; i < 2; i++) {
            int id = tid + i * 256;
            int row = id >> 4;
            int c4 = (id & 15) * 4;
            rw[i] = *reinterpret_cast<const float4*>(W + (size_t)(kb + row) * ldn + nBase + c4);
        }
    };
    auto storeA = [&]() {
        #pragma unroll
        for (int i = 0; i < 4; i++) {
            int id = tid + i * 256;
            int row = id >> 3;
            int c4 = (id & 7) * 4;
            uint32_t* p = &As[row * ASTR + c4];
            p[0] = f2tf32(ra[i].x);
            p[1] = f2tf32(ra[i].y);
            p[2] = f2tf32(ra[i].z);
            p[3] = f2tf32(ra[i].w);
        }
    };
    auto storeW = [&]() {
        #pragma unroll
        for (int i = 0; i < 2; i++) {
            int id = tid + i * 256;
            int row = id >> 4;
            int c4 = (id & 15) * 4;
            uint32_t* p = &Ws[row * WSTR + c4];
            p[0] = f2tf32(rw[i].x);
            p[1] = f2tf32(rw[i].y);
            p[2] = f2tf32(rw[i].z);
            p[3] = f2tf32(rw[i].w);
        }
    };

    float acc[2][4][4];
    #pragma unroll
    for (int m = 0; m < 2; m++)
        #pragma unroll
        for (int n = 0; n < 4; n++)
            #pragma unroll
            for (int q = 0; q < 4; q++) acc[m][n][q] = 0.f;

    loadA(0);
    loadW(0);

    for (int kb = 0; kb < K; kb += BK) {
        storeA();
        storeW();
        __syncthreads();
        if (kb + BK < K) { loadA(kb + BK); loadW(kb + BK); }

        #pragma unroll
        for (int ks = 0; ks < BK; ks += 8) {
            uint32_t af[2][4];
            #pragma unroll
            for (int m = 0; m < 2; m++) {
                int r0 = warpM + m * 16 + g;
                int r1 = r0 + 8;
                af[m][0] = As[r0 * ASTR + ks + tig];
                af[m][1] = As[r1 * ASTR + ks + tig];
                af[m][2] = As[r0 * ASTR + ks + tig + 4];
                af[m][3] = As[r1 * ASTR + ks + tig + 4];
            }
            uint32_t bf[4][2];
            #pragma unroll
            for (int n = 0; n < 4; n++) {
                int cn = warpN + n * 8 + g;
                bf[n][0] = Ws[(ks + tig) * WSTR + cn];
                bf[n][1] = Ws[(ks + tig + 4) * WSTR + cn];
            }
            #pragma unroll
            for (int m = 0; m < 2; m++)
                #pragma unroll
                for (int n = 0; n < 4; n++)
                    mma_tf32(acc[m][n], af[m][0], af[m][1], af[m][2], af[m][3],
                             bf[n][0], bf[n][1]);
        }
        __syncthreads();
    }

    #pragma unroll
    for (int n = 0; n < 4; n++) {
        int col = nBase + warpN + n * 8 + tig * 2;
        float bv0 = bias[col];
        float bv1 = bias[col + 1];
        #pragma unroll
        for (int m = 0; m < 2; m++) {
            #pragma unroll
            for (int hf = 0; hf < 2; hf++) {
                int row = rowBase + warpM + m * 16 + g + hf * 8;
                if (row >= M) continue;
                float sc = PSCALE ? pscale[row] : 1.f;
                float o0 = acc[m][n][hf * 2 + 0] + bv0;
                float o1 = acc[m][n][hf * 2 + 1] + bv1;
                if (RELU) { o0 = fmaxf(o0, 0.f); o1 = fmaxf(o1, 0.f); }
                o0 *= sc; o1 *= sc;
                if (OUTH) {
                    __half2 o = __floats2half2_rn(o0, o1);
                    *reinterpret_cast<__half2*>((__half*)Cout + (size_t)row * ldn + col) = o;
                } else {
                    *reinterpret_cast<float2*>((float*)Cout + (size_t)row * ldn + col) =
                        make_float2(o0, o1);
                }
            }
        }
    }
}

// ---------------------------------------------------------------------------
extern "C" void kernel_launch(void* const* d_in, const int* in_sizes, int n_in,
                              void* d_out, int out_size) {
    const float* x   = (const float*)d_in[0];
    const int*   src = (const int*)d_in[1];
    const int*   dst = (const int*)d_in[2];
    const float* w1  = (const float*)d_in[3];
    const float* b1  = (const float*)d_in[4];
    const float* w2  = (const float*)d_in[5];
    const float* b2  = (const float*)d_in[6];
    const float* wm1 = (const float*)d_in[7];
    const float* bm1 = (const float*)d_in[8];
    const float* wm2 = (const float*)d_in[9];
    const float* bm2 = (const float*)d_in[10];

    const int n = in_sizes[0] / 128;
    const int e = in_sizes[1];

    int *deg_in, *deg_out, *row_ptr, *cursor, *sorted_src;
    float *onorm, *inorm, *agg, *h, *h3;
    __half *xh, *h1h;
    cudaGetSymbolAddress((void**)&deg_in, g_deg_in);
    cudaGetSymbolAddress((void**)&deg_out, g_deg_out);
    cudaGetSymbolAddress((void**)&row_ptr, g_row_ptr);
    cudaGetSymbolAddress((void**)&cursor, g_cursor);
    cudaGetSymbolAddress((void**)&sorted_src, g_sorted_src);
    cudaGetSymbolAddress((void**)&onorm, g_out_norm);
    cudaGetSymbolAddress((void**)&inorm, g_in_norm);
    cudaGetSymbolAddress((void**)&xh, g_xh);
    cudaGetSymbolAddress((void**)&h1h, g_h1h);
    cudaGetSymbolAddress((void**)&agg, g_agg);
    cudaGetSymbolAddress((void**)&h, g_h);
    cudaGetSymbolAddress((void**)&h3, g_h3);

    const int nb = (n + 255) / 256;
    const int eb = (e + 511) / 512;

    // --- CSR build ---
    zero_deg_kernel<<<nb, 256>>>(n, deg_in, deg_out);
    hist_kernel<<<eb, 512>>>(e, src, dst, deg_in, deg_out);
    scan_kernel<<<1, 1024>>>(n, deg_in, row_ptr);
    finalize_kernel<<<nb, 256>>>(n, deg_out, deg_in, row_ptr, onorm, inorm, cursor);
    scatter_kernel<<<eb, 512>>>(e, src, dst, cursor, sorted_src);

    // --- x -> fp16 prescaled by out_norm ---
    convert_x_kernel<<<(n * 32 + 255) / 256, 256>>>(n, x, onorm, xh);

    const int aggBlocks = (n + 7) / 8;
    const dim3 g2((n + 127) / 128, 2);
    const dim3 g4((n + 127) / 128, 4);
    const dim3 g1((n + 127) / 128, 1);

    // --- conv1: agg(xh) * in_norm @ w1 + b1, relu, * out_norm -> fp16 ---
    agg_hpair_kernel<<<aggBlocks, 256>>>(n, xh, row_ptr, sorted_src, inorm, agg);
    gemm_tf32_kernel<true, true, true><<<g2, 256>>>(n, 128, 128, agg, w1, b1, onorm, h1h);

    // --- conv2: agg(h1h) * in_norm @ w2 + b2, relu -> fp32 ---
    agg_hpair_kernel<<<aggBlocks, 256>>>(n, h1h, row_ptr, sorted_src, inorm, agg);
    gemm_tf32_kernel<true, false, false><<<g2, 256>>>(n, 128, 128, agg, w2, b2, nullptr, h);

    // --- MLP ---
    gemm_tf32_kernel<true, false, false><<<g4, 256>>>(n, 128, 256, h, wm1, bm1, nullptr, h3);
    gemm_tf32_kernel<false, false, false><<<g1, 256>>>(n, 256, 64, h3, wm2, bm2, nullptr, d_out);
}